// round 1
// baseline (speedup 1.0000x reference)
#include <cuda_runtime.h>

#define NN 20000
#define NE 320000
#define H 128
#define DE 32
#define NL 4

// ---------------- scratch (device globals; no allocations allowed) ----------
__device__ float g_radial[NE];
__device__ float g_P[NN * H];
__device__ float g_Q[NN * H];
__device__ float g_agg[NN * H];
__device__ float g_h[NN * H];

// ---------------- helpers ----------------------------------------------------
__device__ __forceinline__ float siluf(float x) {
    return x * (1.0f / (1.0f + __expf(-x)));
}
__device__ __forceinline__ void fma4(float4& a, float s, float4 w) {
    a.x = fmaf(s, w.x, a.x);
    a.y = fmaf(s, w.y, a.y);
    a.z = fmaf(s, w.z, a.z);
    a.w = fmaf(s, w.w, a.w);
}
__device__ __forceinline__ float4 add4(float4 a, float4 b) {
    return make_float4(a.x + b.x, a.y + b.y, a.z + b.z, a.w + b.w);
}
__device__ __forceinline__ float4 silu4(float4 v) {
    v.x = siluf(v.x); v.y = siluf(v.y); v.z = siluf(v.z); v.w = siluf(v.w);
    return v;
}

// ---------------- tiny utility kernels ---------------------------------------
__global__ void k_copy_h(const float* __restrict__ h) {
    int i = blockIdx.x * blockDim.x + threadIdx.x;   // NN*H/4 threads
    ((float4*)g_h)[i] = ((const float4*)h)[i];
}

__global__ void k_zero_agg() {
    int i = blockIdx.x * blockDim.x + threadIdx.x;
    ((float4*)g_agg)[i] = make_float4(0.f, 0.f, 0.f, 0.f);
}

__global__ void k_radial(const float* __restrict__ coords, const int* __restrict__ edges) {
    int e = blockIdx.x * blockDim.x + threadIdx.x;
    if (e >= NE) return;
    int r = edges[e], c = edges[NE + e];
    float dx = coords[3 * r]     - coords[3 * c];
    float dy = coords[3 * r + 1] - coords[3 * c + 1];
    float dz = coords[3 * r + 2] - coords[3 * c + 2];
    g_radial[e] = dx * dx + dy * dy + dz * dz;
}

// ---------------- P/Q precompute: P = h @ W1[0:128], Q = h @ W1[128:256] ------
// blockIdx.y: 0 -> P, 1 -> Q. Tile: 64 nodes x 128 outputs, 256 threads.
__global__ __launch_bounds__(256) void k_pq(const float* __restrict__ ew1) {
    __shared__ float As[64][36];
    __shared__ float Bs[32][128];
    const float* B = ew1 + (size_t)blockIdx.y * H * H;
    float* C = blockIdx.y ? g_Q : g_P;
    int tid = threadIdx.x;
    int mg = tid >> 4, fg = tid & 15;
    int m0 = blockIdx.x * 64;

    float4 acc0[4], acc1[4];
#pragma unroll
    for (int i = 0; i < 4; i++) {
        acc0[i] = make_float4(0.f, 0.f, 0.f, 0.f);
        acc1[i] = make_float4(0.f, 0.f, 0.f, 0.f);
    }

    for (int c = 0; c < 4; c++) {
#pragma unroll
        for (int i = 0; i < 2; i++) {
            int id = tid * 2 + i;
            int r = id >> 3, cv = id & 7;
            int n = m0 + r;
            float4 v = (n < NN) ? ((const float4*)(g_h + (size_t)n * H + c * 32))[cv]
                                : make_float4(0.f, 0.f, 0.f, 0.f);
            ((float4*)&As[r][0])[cv] = v;
        }
#pragma unroll
        for (int i = 0; i < 4; i++) {
            int id = tid + 256 * i;
            int r = id >> 5, cv = id & 31;
            ((float4*)&Bs[r][0])[cv] = ((const float4*)(B + (size_t)(c * 32 + r) * H))[cv];
        }
        __syncthreads();
#pragma unroll
        for (int k = 0; k < 32; k++) {
            float4 w0 = ((const float4*)&Bs[k][0])[fg];
            float4 w1 = ((const float4*)&Bs[k][0])[fg + 16];
#pragma unroll
            for (int i = 0; i < 4; i++) {
                float a = As[mg * 4 + i][k];
                fma4(acc0[i], a, w0);
                fma4(acc1[i], a, w1);
            }
        }
        __syncthreads();
    }
#pragma unroll
    for (int i = 0; i < 4; i++) {
        int n = m0 + mg * 4 + i;
        if (n < NN) {
            ((float4*)(C + (size_t)n * H))[fg]      = acc0[i];
            ((float4*)(C + (size_t)n * H))[fg + 16] = acc1[i];
        }
    }
}

// ---------------- edge kernel: the dominant one -------------------------------
// 64 edges per block, 256 threads.
// phase 1: hidden = silu(P[row] + Q[col] + [radial|edge_attr]@W1c + b1)
// phase 2: m = silu(hidden @ W2 + b2)   (register-tiled 4x8, W2 in smem chunks)
// phase 3: atomic float4 scatter-add into g_agg
#define EDGE_SMEM (((64 * 34) + (33 * 132) + (64 * 132) + (32 * 128)) * 4 + 2 * 64 * 4)

__global__ __launch_bounds__(256, 2) void k_edge(
    const int* __restrict__ edges, const float* __restrict__ edge_attr,
    const float* __restrict__ ew1, const float* __restrict__ eb1,
    const float* __restrict__ ew2, const float* __restrict__ eb2) {
    extern __shared__ float sm[];
    float (*xs)[34]    = (float(*)[34])sm;                                   // 64 x 34
    float (*W1cs)[132] = (float(*)[132])(sm + 64 * 34);                      // 33 x 132
    float (*Sh)[132]   = (float(*)[132])(sm + 64 * 34 + 33 * 132);          // 64 x 132
    float (*W2s)[128]  = (float(*)[128])(sm + 64 * 34 + 33 * 132 + 64 * 132); // 32 x 128
    int* rs = (int*)(sm + 64 * 34 + 33 * 132 + 64 * 132 + 32 * 128);
    int* cs = rs + 64;

    int tid = threadIdx.x;
    int e0 = blockIdx.x * 64;

    if (tid < 64) {
        rs[tid] = edges[e0 + tid];
        xs[tid][0] = g_radial[e0 + tid];
    } else if (tid < 128) {
        cs[tid - 64] = edges[NE + e0 + tid - 64];
    }
#pragma unroll
    for (int i = 0; i < 2; i++) {
        int id = tid * 2 + i;
        int e = id >> 3, cv = id & 7;
        float4 v = ((const float4*)(edge_attr + (size_t)(e0 + e) * DE))[cv];
        int b = 1 + cv * 4;
        xs[e][b] = v.x; xs[e][b + 1] = v.y; xs[e][b + 2] = v.z; xs[e][b + 3] = v.w;
    }
#pragma unroll
    for (int i = 0; i < 5; i++) {
        int id = tid + 256 * i;
        if (id < 33 * 32) {
            int r = id >> 5, cv = id & 31;
            ((float4*)&W1cs[r][0])[cv] = ((const float4*)(ew1 + (size_t)(256 + r) * H))[cv];
        }
    }
    __syncthreads();

    // ---- phase 1: 4 threads per edge, 32 features each
    {
        int eh = tid >> 2, fq = tid & 3;
        float4 acc[8];
        const float4* b1p = (const float4*)eb1;
#pragma unroll
        for (int j = 0; j < 8; j++) acc[j] = b1p[fq * 8 + j];
        for (int k = 0; k < 33; k++) {
            float x = xs[eh][k];
            const float4* wr = (const float4*)&W1cs[k][0];
#pragma unroll
            for (int j = 0; j < 8; j++) fma4(acc[j], x, wr[fq * 8 + j]);
        }
        int r = rs[eh], c = cs[eh];
        const float4* Pp = ((const float4*)(g_P + (size_t)r * H)) + fq * 8;
        const float4* Qp = ((const float4*)(g_Q + (size_t)c * H)) + fq * 8;
#pragma unroll
        for (int j = 0; j < 8; j++) {
            float4 v = add4(add4(acc[j], Pp[j]), Qp[j]);
            ((float4*)&Sh[eh][0])[fq * 8 + j] = silu4(v);
        }
    }
    __syncthreads();

    // ---- phase 2: hidden @ W2 ; thread = 4 edges x (4+4) feats
    int mg = tid >> 4, fg = tid & 15;
    float4 acc0[4], acc1[4];
#pragma unroll
    for (int i = 0; i < 4; i++) {
        acc0[i] = make_float4(0.f, 0.f, 0.f, 0.f);
        acc1[i] = make_float4(0.f, 0.f, 0.f, 0.f);
    }
    for (int cch = 0; cch < 4; cch++) {
#pragma unroll
        for (int i = 0; i < 4; i++) {
            int id = tid + 256 * i;
            int r = id >> 5, cv = id & 31;
            ((float4*)&W2s[r][0])[cv] = ((const float4*)(ew2 + (size_t)(cch * 32 + r) * H))[cv];
        }
        __syncthreads();
#pragma unroll
        for (int k = 0; k < 32; k++) {
            float4 w0 = ((const float4*)&W2s[k][0])[fg];
            float4 w1 = ((const float4*)&W2s[k][0])[fg + 16];
#pragma unroll
            for (int i = 0; i < 4; i++) {
                float a = Sh[mg * 4 + i][cch * 32 + k];
                fma4(acc0[i], a, w0);
                fma4(acc1[i], a, w1);
            }
        }
        __syncthreads();
    }

    // ---- phase 3: silu + vector scatter-add
    float4 b20 = ((const float4*)eb2)[fg];
    float4 b21 = ((const float4*)eb2)[fg + 16];
#pragma unroll
    for (int i = 0; i < 4; i++) {
        int r = rs[mg * 4 + i];
        float4 m0 = silu4(add4(acc0[i], b20));
        float4 m1 = silu4(add4(acc1[i], b21));
        atomicAdd((float4*)(g_agg + (size_t)r * H + fg * 4), m0);
        atomicAdd((float4*)(g_agg + (size_t)r * H + 64 + fg * 4), m1);
    }
}

// ---------------- node kernel: fused [h|agg]@nw1 -> silu -> @nw2 (+res) -------
#define NODE_SMEM (((64 * 36) + (32 * 128) + (64 * 132)) * 4)

__global__ __launch_bounds__(256) void k_node(
    const float* __restrict__ nw1, const float* __restrict__ nb1,
    const float* __restrict__ nw2, const float* __restrict__ nb2,
    int residual) {
    extern __shared__ float sm[];
    float (*As)[36]  = (float(*)[36])sm;                       // 64 x 36
    float (*Bs)[128] = (float(*)[128])(sm + 64 * 36);          // 32 x 128
    float (*Ss)[132] = (float(*)[132])(sm + 64 * 36 + 32 * 128); // 64 x 132

    int tid = threadIdx.x;
    int mg = tid >> 4, fg = tid & 15;
    int m0 = blockIdx.x * 64;

    float4 acc0[4], acc1[4];
#pragma unroll
    for (int i = 0; i < 4; i++) {
        acc0[i] = make_float4(0.f, 0.f, 0.f, 0.f);
        acc1[i] = make_float4(0.f, 0.f, 0.f, 0.f);
    }

    // GEMM1 over K=256 (h cols 0..127 then agg cols 0..127)
    for (int c = 0; c < 8; c++) {
        const float* Asrc = (c < 4) ? g_h : g_agg;
        int koff = (c & 3) * 32;
#pragma unroll
        for (int i = 0; i < 2; i++) {
            int id = tid * 2 + i;
            int r = id >> 3, cv = id & 7;
            int n = m0 + r;
            float4 v = (n < NN) ? ((const float4*)(Asrc + (size_t)n * H + koff))[cv]
                                : make_float4(0.f, 0.f, 0.f, 0.f);
            ((float4*)&As[r][0])[cv] = v;
        }
#pragma unroll
        for (int i = 0; i < 4; i++) {
            int id = tid + 256 * i;
            int r = id >> 5, cv = id & 31;
            ((float4*)&Bs[r][0])[cv] = ((const float4*)(nw1 + (size_t)(c * 32 + r) * H))[cv];
        }
        __syncthreads();
#pragma unroll
        for (int k = 0; k < 32; k++) {
            float4 w0 = ((const float4*)&Bs[k][0])[fg];
            float4 w1 = ((const float4*)&Bs[k][0])[fg + 16];
#pragma unroll
            for (int i = 0; i < 4; i++) {
                float a = As[mg * 4 + i][k];
                fma4(acc0[i], a, w0);
                fma4(acc1[i], a, w1);
            }
        }
        __syncthreads();
    }

    {
        float4 b0  = ((const float4*)nb1)[fg];
        float4 b1v = ((const float4*)nb1)[fg + 16];
#pragma unroll
        for (int i = 0; i < 4; i++) {
            ((float4*)&Ss[mg * 4 + i][0])[fg]      = silu4(add4(acc0[i], b0));
            ((float4*)&Ss[mg * 4 + i][0])[fg + 16] = silu4(add4(acc1[i], b1v));
            acc0[i] = make_float4(0.f, 0.f, 0.f, 0.f);
            acc1[i] = make_float4(0.f, 0.f, 0.f, 0.f);
        }
    }
    __syncthreads();

    // GEMM2 over K=128
    for (int c = 0; c < 4; c++) {
#pragma unroll
        for (int i = 0; i < 4; i++) {
            int id = tid + 256 * i;
            int r = id >> 5, cv = id & 31;
            ((float4*)&Bs[r][0])[cv] = ((const float4*)(nw2 + (size_t)(c * 32 + r) * H))[cv];
        }
        __syncthreads();
#pragma unroll
        for (int k = 0; k < 32; k++) {
            float4 w0 = ((const float4*)&Bs[k][0])[fg];
            float4 w1 = ((const float4*)&Bs[k][0])[fg + 16];
#pragma unroll
            for (int i = 0; i < 4; i++) {
                float a = Ss[mg * 4 + i][c * 32 + k];
                fma4(acc0[i], a, w0);
                fma4(acc1[i], a, w1);
            }
        }
        __syncthreads();
    }

    float4 b20 = ((const float4*)nb2)[fg];
    float4 b21 = ((const float4*)nb2)[fg + 16];
#pragma unroll
    for (int i = 0; i < 4; i++) {
        int n = m0 + mg * 4 + i;
        if (n < NN) {
            float4 o0 = add4(acc0[i], b20);
            float4 o1 = add4(acc1[i], b21);
            if (residual) {
                o0 = add4(o0, ((const float4*)(g_h + (size_t)n * H))[fg]);
                o1 = add4(o1, ((const float4*)(g_h + (size_t)n * H))[fg + 16]);
            }
            ((float4*)(g_h + (size_t)n * H))[fg]      = o0;
            ((float4*)(g_h + (size_t)n * H))[fg + 16] = o1;
        }
    }
}

// ---------------- final LayerNorm --------------------------------------------
__global__ void k_ln(const float* __restrict__ gam, const float* __restrict__ bet,
                     float* __restrict__ out) {
    int gw = (blockIdx.x * blockDim.x + threadIdx.x) >> 5;
    int lane = threadIdx.x & 31;
    if (gw >= NN) return;
    const float* hr = g_h + (size_t)gw * H;
    float v[4];
    float s = 0.f;
#pragma unroll
    for (int j = 0; j < 4; j++) { v[j] = hr[lane + 32 * j]; s += v[j]; }
#pragma unroll
    for (int o = 16; o > 0; o >>= 1) s += __shfl_xor_sync(0xffffffffu, s, o);
    float mu = s * (1.f / 128.f);
    float vs = 0.f;
#pragma unroll
    for (int j = 0; j < 4; j++) { float d = v[j] - mu; vs += d * d; }
#pragma unroll
    for (int o = 16; o > 0; o >>= 1) vs += __shfl_xor_sync(0xffffffffu, vs, o);
    float inv = rsqrtf(vs * (1.f / 128.f) + 1e-5f);
#pragma unroll
    for (int j = 0; j < 4; j++) {
        int f = lane + 32 * j;
        out[(size_t)gw * H + f] = (v[j] - mu) * inv * gam[f] + bet[f];
    }
}

// ---------------- launch -------------------------------------------------------
extern "C" void kernel_launch(void* const* d_in, const int* in_sizes, int n_in,
                              void* d_out, int out_size) {
    const float* h   = (const float*)d_in[0];
    const float* co  = (const float*)d_in[1];
    const float* ea  = (const float*)d_in[2];
    const int*   ed  = (const int*)d_in[3];
    const float* ew1 = (const float*)d_in[4];
    const float* eb1 = (const float*)d_in[5];
    const float* ew2 = (const float*)d_in[6];
    const float* eb2 = (const float*)d_in[7];
    const float* nw1 = (const float*)d_in[8];
    const float* nb1 = (const float*)d_in[9];
    const float* nw2 = (const float*)d_in[10];
    const float* nb2 = (const float*)d_in[11];
    const float* lng = (const float*)d_in[12];
    const float* lnb = (const float*)d_in[13];
    float* out = (float*)d_out;

    cudaFuncSetAttribute(k_edge, cudaFuncAttributeMaxDynamicSharedMemorySize, EDGE_SMEM);
    cudaFuncSetAttribute(k_node, cudaFuncAttributeMaxDynamicSharedMemorySize, NODE_SMEM);

    k_copy_h<<<2500, 256>>>(h);      // NN*H/4 / 256
    k_radial<<<1250, 256>>>(co, ed); // NE / 256

    for (int i = 0; i < NL; i++) {
        const float* ew1i = ew1 + (size_t)i * 289 * H;
        k_zero_agg<<<2500, 256>>>();
        k_pq<<<dim3(313, 2), 256>>>(ew1i);
        k_edge<<<NE / 64, 256, EDGE_SMEM>>>(ed, ea, ew1i,
                                            eb1 + i * H,
                                            ew2 + (size_t)i * H * H,
                                            eb2 + i * H);
        k_node<<<313, 256, NODE_SMEM>>>(nw1 + (size_t)i * 2 * H * H,
                                        nb1 + i * H,
                                        nw2 + (size_t)i * H * H,
                                        nb2 + i * H,
                                        i > 0);
    }
    k_ln<<<2500, 256>>>(lng, lnb, out);
}

// round 3
// speedup vs baseline: 1.1067x; 1.1067x over previous
#include <cuda_runtime.h>
#include <cstdint>

#define NN 20000
#define NE 320000
#define H 128
#define DE 32
#define NL 4

// ---------------- scratch (device globals) -----------------------------------
__device__ float g_radial[NE];
__device__ float g_P[NN * H];
__device__ float g_Q[NN * H];
__device__ float g_agg[NN * H];
__device__ float g_h[NN * H];
// tf32-rounded weight copies
__device__ float g_ew1t[NL * 289 * H];
__device__ float g_w2t[NL * H * H];
__device__ float g_nw1t[NL * 2 * H * H];
__device__ float g_nw2t[NL * H * H];

// ---------------- helpers -----------------------------------------------------
__device__ __forceinline__ float siluf(float x) {
    return x * (1.0f / (1.0f + __expf(-x)));
}
__device__ __forceinline__ void fma4(float4& a, float s, float4 w) {
    a.x = fmaf(s, w.x, a.x); a.y = fmaf(s, w.y, a.y);
    a.z = fmaf(s, w.z, a.z); a.w = fmaf(s, w.w, a.w);
}
__device__ __forceinline__ float4 add4(float4 a, float4 b) {
    return make_float4(a.x + b.x, a.y + b.y, a.z + b.z, a.w + b.w);
}
__device__ __forceinline__ float4 silu4(float4 v) {
    v.x = siluf(v.x); v.y = siluf(v.y); v.z = siluf(v.z); v.w = siluf(v.w);
    return v;
}
__device__ __forceinline__ float tf32r(float x) {
    unsigned int u;
    asm("cvt.rna.tf32.f32 %0, %1;" : "=r"(u) : "f"(x));
    return __uint_as_float(u);
}
__device__ __forceinline__ unsigned int fb(float x) { return __float_as_uint(x); }

__device__ __forceinline__ void mma8(float* d, unsigned int a0, unsigned int a1,
                                     unsigned int a2, unsigned int a3,
                                     unsigned int b0, unsigned int b1) {
    asm volatile(
        "mma.sync.aligned.m16n8k8.row.col.f32.tf32.tf32.f32 "
        "{%0,%1,%2,%3},{%4,%5,%6,%7},{%8,%9},{%0,%1,%2,%3};\n"
        : "+f"(d[0]), "+f"(d[1]), "+f"(d[2]), "+f"(d[3])
        : "r"(a0), "r"(a1), "r"(a2), "r"(a3), "r"(b0), "r"(b1));
}

// ---------------- tiny utility kernels ----------------------------------------
__global__ void k_copy_h(const float* __restrict__ h) {
    int i = blockIdx.x * blockDim.x + threadIdx.x;
    ((float4*)g_h)[i] = ((const float4*)h)[i];
}
__global__ void k_zero_agg() {
    int i = blockIdx.x * blockDim.x + threadIdx.x;
    ((float4*)g_agg)[i] = make_float4(0.f, 0.f, 0.f, 0.f);
}
__global__ void k_radial(const float* __restrict__ coords, const int* __restrict__ edges) {
    int e = blockIdx.x * blockDim.x + threadIdx.x;
    if (e >= NE) return;
    int r = edges[e], c = edges[NE + e];
    float dx = coords[3 * r]     - coords[3 * c];
    float dy = coords[3 * r + 1] - coords[3 * c + 1];
    float dz = coords[3 * r + 2] - coords[3 * c + 2];
    g_radial[e] = dx * dx + dy * dy + dz * dz;
}
// convert a weight tensor to tf32-rounded copy. sel: 0 ew1, 1 w2, 2 nw1, 3 nw2
__global__ void k_cvt(const float* __restrict__ src, int n, int sel) {
    float* dst = (sel == 0) ? g_ew1t : (sel == 1) ? g_w2t : (sel == 2) ? g_nw1t : g_nw2t;
    for (int i = blockIdx.x * blockDim.x + threadIdx.x; i < n; i += gridDim.x * blockDim.x)
        dst[i] = tf32r(src[i]);
}

// ---------------- k_pq: P = h @ W1a, Q = h @ W1b (tf32 mma) -------------------
// block: 256 thr, 64 nodes x 128 outs. grid (313, 2).
#define PQ_SMEM ((64 * 132 + 128 * 132) * 4)
__global__ __launch_bounds__(256) void k_pq(int lyr) {
    extern __shared__ float sm[];
    float* As = sm;                 // [64][132] tf32(h)
    float* Bs = sm + 64 * 132;      // [128][132] tf32 weights
    int tid = threadIdx.x;
    int m0 = blockIdx.x * 64;
    const float* B = g_ew1t + (size_t)lyr * 289 * H + (size_t)blockIdx.y * H * H;
    float* C = blockIdx.y ? g_Q : g_P;

#pragma unroll
    for (int i = 0; i < 8; i++) {       // A: 64 x 32 float4
        int id = tid + 256 * i;
        int r = id >> 5, cv = id & 31;
        int n = m0 + r;
        float4 v = (n < NN) ? ((const float4*)(g_h + (size_t)n * H))[cv]
                            : make_float4(0.f, 0.f, 0.f, 0.f);
        v.x = tf32r(v.x); v.y = tf32r(v.y); v.z = tf32r(v.z); v.w = tf32r(v.w);
        ((float4*)(As + r * 132))[cv] = v;
    }
#pragma unroll
    for (int i = 0; i < 16; i++) {      // B: 128 x 32 float4
        int id = tid + 256 * i;
        int r = id >> 5, cv = id & 31;
        ((float4*)(Bs + r * 132))[cv] = ((const float4*)(B + (size_t)r * H))[cv];
    }
    __syncthreads();

    int wid = tid >> 5, lane = tid & 31;
    int warpM = wid & 3, warpN = wid >> 2;
    int g = lane >> 2, t = lane & 3;
    int r0 = warpM * 16, n0 = warpN * 64;
    const float* A0 = As + (r0 + g) * 132;
    const float* A1 = As + (r0 + g + 8) * 132;
    const float* Bp = Bs + t * 132 + n0 + g;

    float acc[8][4];
#pragma unroll
    for (int nf = 0; nf < 8; nf++)
#pragma unroll
        for (int j = 0; j < 4; j++) acc[nf][j] = 0.f;

#pragma unroll
    for (int k0 = 0; k0 < 128; k0 += 8) {
        unsigned int a0 = fb(A0[k0 + t]),     a1 = fb(A1[k0 + t]);
        unsigned int a2 = fb(A0[k0 + t + 4]), a3 = fb(A1[k0 + t + 4]);
#pragma unroll
        for (int nf = 0; nf < 8; nf++) {
            unsigned int b0 = fb(Bp[k0 * 132 + nf * 8]);
            unsigned int b1 = fb(Bp[(k0 + 4) * 132 + nf * 8]);
            mma8(acc[nf], a0, a1, a2, a3, b0, b1);
        }
    }
    int ng  = m0 + r0 + g;
    int ng8 = ng + 8;
#pragma unroll
    for (int nf = 0; nf < 8; nf++) {
        int col = n0 + nf * 8 + 2 * t;
        if (ng < NN)
            *(float2*)(C + (size_t)ng * H + col)  = make_float2(acc[nf][0], acc[nf][1]);
        if (ng8 < NN)
            *(float2*)(C + (size_t)ng8 * H + col) = make_float2(acc[nf][2], acc[nf][3]);
    }
}

// ---------------- k_edge -------------------------------------------------------
// 128 edges/block, 512 threads.
// phase1 (fp32): hidden = silu(P[row]+Q[col]+X@W1c+b1) -> Sh (tf32-rounded)
// phase2 (tf32 mma): m = Sh @ W2
// phase3: silu(+b2), shfl-packed float4 atomic scatter into g_agg
#define EDGE_SMEM ((128 * 34 + 33 * 132 + 128 * 132 + 128 * 132) * 4 + 2 * 128 * 4)

__global__ __launch_bounds__(512) void k_edge(
    const int* __restrict__ edges, const float* __restrict__ edge_attr,
    const float* __restrict__ ew1, const float* __restrict__ eb1,
    const float* __restrict__ eb2, int lyr) {
    extern __shared__ float sm[];
    float* xs   = sm;                               // [128][34]
    float* W1cs = sm + 128 * 34;                    // [33][132] fp32
    float* Sh   = W1cs + 33 * 132;                  // [128][132] tf32 vals
    float* W2s  = Sh + 128 * 132;                   // [128][132] tf32 vals
    int*   rs   = (int*)(W2s + 128 * 132);          // [128]
    int*   cs   = rs + 128;

    int tid = threadIdx.x;
    int e0 = blockIdx.x * 128;

    // ---- phase 0: stage everything
    if (tid < 128) {
        rs[tid] = edges[e0 + tid];
        xs[tid * 34] = g_radial[e0 + tid];
    } else if (tid < 256) {
        cs[tid - 128] = edges[NE + e0 + tid - 128];
    }
#pragma unroll
    for (int i = 0; i < 2; i++) {                   // edge_attr: 128 x 8 float4
        int id = tid + 512 * i;
        int e = id >> 3, cv = id & 7;
        float4 v = ((const float4*)(edge_attr + (size_t)(e0 + e) * DE))[cv];
        float* xp = xs + e * 34 + 1 + cv * 4;
        xp[0] = v.x; xp[1] = v.y; xp[2] = v.z; xp[3] = v.w;
    }
#pragma unroll
    for (int i = 0; i < 3; i++) {                   // W1c: 33 x 32 float4 (fp32)
        int id = tid + 512 * i;
        if (id < 33 * 32) {
            int r = id >> 5, cv = id & 31;
            ((float4*)(W1cs + r * 132))[cv] =
                ((const float4*)(ew1 + (size_t)(256 + r) * H))[cv];
        }
    }
    {
        const float* W2 = g_w2t + (size_t)lyr * H * H;
#pragma unroll
        for (int i = 0; i < 9; i++) {               // W2: 128 x 32 float4 (tf32)
            int id = tid + 512 * i;
            if (id < 128 * 32) {
                int r = id >> 5, cv = id & 31;
                ((float4*)(W2s + r * 132))[cv] = ((const float4*)(W2 + (size_t)r * H))[cv];
            }
        }
    }
    __syncthreads();

    // ---- phase 1: fp32, 4 threads/edge, 32 feats each
    {
        int eh = tid >> 2, fq = tid & 3;
        float4 acc[8];
        const float4* b1p = (const float4*)eb1;
#pragma unroll
        for (int j = 0; j < 8; j++) acc[j] = b1p[fq * 8 + j];
        const float* xrow = xs + eh * 34;
        for (int k = 0; k < 33; k++) {
            float x = xrow[k];
            const float4* wr = (const float4*)(W1cs + k * 132);
#pragma unroll
            for (int j = 0; j < 8; j++) fma4(acc[j], x, wr[fq * 8 + j]);
        }
        int r = rs[eh], c = cs[eh];
        const float4* Pp = ((const float4*)(g_P + (size_t)r * H)) + fq * 8;
        const float4* Qp = ((const float4*)(g_Q + (size_t)c * H)) + fq * 8;
        float* Srow = Sh + eh * 132 + fq * 32;
#pragma unroll
        for (int j = 0; j < 8; j++) {
            float4 v = silu4(add4(add4(acc[j], Pp[j]), Qp[j]));
            Srow[j * 4]     = tf32r(v.x);
            Srow[j * 4 + 1] = tf32r(v.y);
            Srow[j * 4 + 2] = tf32r(v.z);
            Srow[j * 4 + 3] = tf32r(v.w);
        }
    }
    __syncthreads();

    // ---- phase 2: tf32 mma, 16 warps: 8 x M16, 2 x N64
    int wid = tid >> 5, lane = tid & 31;
    int warpM = wid & 7, warpN = wid >> 3;
    int g = lane >> 2, t = lane & 3;
    int r0 = warpM * 16, n0 = warpN * 64;
    const float* A0 = Sh + (r0 + g) * 132;
    const float* A1 = Sh + (r0 + g + 8) * 132;
    const float* Bp = W2s + t * 132 + n0 + g;

    float acc[8][4];
#pragma unroll
    for (int nf = 0; nf < 8; nf++)
#pragma unroll
        for (int j = 0; j < 4; j++) acc[nf][j] = 0.f;

#pragma unroll
    for (int k0 = 0; k0 < 128; k0 += 8) {
        unsigned int a0 = fb(A0[k0 + t]),     a1 = fb(A1[k0 + t]);
        unsigned int a2 = fb(A0[k0 + t + 4]), a3 = fb(A1[k0 + t + 4]);
#pragma unroll
        for (int nf = 0; nf < 8; nf++) {
            unsigned int b0 = fb(Bp[k0 * 132 + nf * 8]);
            unsigned int b1 = fb(Bp[(k0 + 4) * 132 + nf * 8]);
            mma8(acc[nf], a0, a1, a2, a3, b0, b1);
        }
    }

    // ---- phase 3: pack via shfl, bias+silu, float4 atomic scatter
    {
        bool odd = (t & 1);
        int node = odd ? rs[r0 + g + 8] : rs[r0 + g];
#pragma unroll
        for (int nf = 0; nf < 8; nf++) {
            float px = odd ? acc[nf][0] : acc[nf][2];
            float py = odd ? acc[nf][1] : acc[nf][3];
            float rx = __shfl_xor_sync(0xffffffffu, px, 1);
            float ry = __shfl_xor_sync(0xffffffffu, py, 1);
            float4 v;
            int col;
            if (!odd) {
                v = make_float4(acc[nf][0], acc[nf][1], rx, ry);
                col = n0 + nf * 8 + 2 * t;
            } else {
                v = make_float4(rx, ry, acc[nf][2], acc[nf][3]);
                col = n0 + nf * 8 + 2 * (t - 1);
            }
            float4 b = *(const float4*)(eb2 + col);
            v = silu4(add4(v, b));
            atomicAdd((float4*)(g_agg + (size_t)node * H + col), v);
        }
    }
}

// ---------------- k_node: fused [h|agg]@nw1 -> silu -> @nw2 (+res), tf32 mma --
#define NODE_SMEM ((64 * 260 + 256 * 132) * 4)
__global__ __launch_bounds__(256) void k_node(
    const float* __restrict__ nb1, const float* __restrict__ nb2,
    int lyr, int residual) {
    extern __shared__ float sm[];
    float* As  = sm;                  // [64][260] tf32([h|agg]); later Ss [64][132]
    float* Bs  = sm + 64 * 260;       // [256][132] nw1t; later [128][132] nw2t
    int tid = threadIdx.x;
    int m0 = blockIdx.x * 64;

#pragma unroll
    for (int i = 0; i < 16; i++) {    // A: 64 rows x 64 float4 (h then agg)
        int id = tid + 256 * i;
        int r = id >> 6, cv = id & 63;
        int n = m0 + r;
        const float* src = (cv < 32) ? (g_h + (size_t)n * H + cv * 4)
                                     : (g_agg + (size_t)n * H + (cv - 32) * 4);
        float4 v = (n < NN) ? *(const float4*)src : make_float4(0.f, 0.f, 0.f, 0.f);
        v.x = tf32r(v.x); v.y = tf32r(v.y); v.z = tf32r(v.z); v.w = tf32r(v.w);
        float* dst = As + r * 260 + cv * 4;
        dst[0] = v.x; dst[1] = v.y; dst[2] = v.z; dst[3] = v.w;
    }
    {
        const float* B = g_nw1t + (size_t)lyr * 2 * H * H;
#pragma unroll
        for (int i = 0; i < 32; i++) { // B1: 256 x 32 float4
            int id = tid + 256 * i;
            int r = id >> 5, cv = id & 31;
            ((float4*)(Bs + r * 132))[cv] = ((const float4*)(B + (size_t)r * H))[cv];
        }
    }
    __syncthreads();

    int wid = tid >> 5, lane = tid & 31;
    int warpM = wid & 3, warpN = wid >> 2;
    int g = lane >> 2, t = lane & 3;
    int r0 = warpM * 16, n0 = warpN * 64;

    float acc[8][4];
#pragma unroll
    for (int nf = 0; nf < 8; nf++)
#pragma unroll
        for (int j = 0; j < 4; j++) acc[nf][j] = 0.f;

    {   // GEMM1: K = 256
        const float* A0 = As + (r0 + g) * 260;
        const float* A1 = As + (r0 + g + 8) * 260;
        const float* Bp = Bs + t * 132 + n0 + g;
#pragma unroll
        for (int k0 = 0; k0 < 256; k0 += 8) {
            unsigned int a0 = fb(A0[k0 + t]),     a1 = fb(A1[k0 + t]);
            unsigned int a2 = fb(A0[k0 + t + 4]), a3 = fb(A1[k0 + t + 4]);
#pragma unroll
            for (int nf = 0; nf < 8; nf++) {
                unsigned int b0 = fb(Bp[k0 * 132 + nf * 8]);
                unsigned int b1 = fb(Bp[(k0 + 4) * 132 + nf * 8]);
                mma8(acc[nf], a0, a1, a2, a3, b0, b1);
            }
        }
    }
    __syncthreads();   // As no longer needed; Bs1 no longer needed

    // epilogue 1: silu(+b1) -> Ss (tf32), and load Bs2
    {
        float* Ss = As;   // [64][132]
#pragma unroll
        for (int nf = 0; nf < 8; nf++) {
            int col = n0 + nf * 8 + 2 * t;
            float2 b = *(const float2*)(nb1 + col);
            float* s0 = Ss + (r0 + g) * 132 + col;
            float* s1 = Ss + (r0 + g + 8) * 132 + col;
            s0[0] = tf32r(siluf(acc[nf][0] + b.x));
            s0[1] = tf32r(siluf(acc[nf][1] + b.y));
            s1[0] = tf32r(siluf(acc[nf][2] + b.x));
            s1[1] = tf32r(siluf(acc[nf][3] + b.y));
        }
        const float* B = g_nw2t + (size_t)lyr * H * H;
#pragma unroll
        for (int i = 0; i < 16; i++) { // B2: 128 x 32 float4
            int id = tid + 256 * i;
            int r = id >> 5, cv = id & 31;
            ((float4*)(Bs + r * 132))[cv] = ((const float4*)(B + (size_t)r * H))[cv];
        }
    }
    __syncthreads();

    {   // GEMM2: K = 128
#pragma unroll
        for (int nf = 0; nf < 8; nf++)
#pragma unroll
            for (int j = 0; j < 4; j++) acc[nf][j] = 0.f;
        const float* Ss = As;
        const float* A0 = Ss + (r0 + g) * 132;
        const float* A1 = Ss + (r0 + g + 8) * 132;
        const float* Bp = Bs + t * 132 + n0 + g;
#pragma unroll
        for (int k0 = 0; k0 < 128; k0 += 8) {
            unsigned int a0 = fb(A0[k0 + t]),     a1 = fb(A1[k0 + t]);
            unsigned int a2 = fb(A0[k0 + t + 4]), a3 = fb(A1[k0 + t + 4]);
#pragma unroll
            for (int nf = 0; nf < 8; nf++) {
                unsigned int b0 = fb(Bp[k0 * 132 + nf * 8]);
                unsigned int b1 = fb(Bp[(k0 + 4) * 132 + nf * 8]);
                mma8(acc[nf], a0, a1, a2, a3, b0, b1);
            }
        }
    }

    // epilogue 2: +b2 (+residual) -> g_h
    int ng  = m0 + r0 + g;
    int ng8 = ng + 8;
#pragma unroll
    for (int nf = 0; nf < 8; nf++) {
        int col = n0 + nf * 8 + 2 * t;
        float2 b = *(const float2*)(nb2 + col);
        if (ng < NN) {
            float2* hp = (float2*)(g_h + (size_t)ng * H + col);
            float2 o = make_float2(acc[nf][0] + b.x, acc[nf][1] + b.y);
            if (residual) { float2 old = *hp; o.x += old.x; o.y += old.y; }
            *hp = o;
        }
        if (ng8 < NN) {
            float2* hp = (float2*)(g_h + (size_t)ng8 * H + col);
            float2 o = make_float2(acc[nf][2] + b.x, acc[nf][3] + b.y);
            if (residual) { float2 old = *hp; o.x += old.x; o.y += old.y; }
            *hp = o;
        }
    }
}

// ---------------- final LayerNorm ---------------------------------------------
__global__ void k_ln(const float* __restrict__ gam, const float* __restrict__ bet,
                     float* __restrict__ out) {
    int gw = (blockIdx.x * blockDim.x + threadIdx.x) >> 5;
    int lane = threadIdx.x & 31;
    if (gw >= NN) return;
    const float* hr = g_h + (size_t)gw * H;
    float v[4];
    float s = 0.f;
#pragma unroll
    for (int j = 0; j < 4; j++) { v[j] = hr[lane + 32 * j]; s += v[j]; }
#pragma unroll
    for (int o = 16; o > 0; o >>= 1) s += __shfl_xor_sync(0xffffffffu, s, o);
    float mu = s * (1.f / 128.f);
    float vs = 0.f;
#pragma unroll
    for (int j = 0; j < 4; j++) { float d = v[j] - mu; vs += d * d; }
#pragma unroll
    for (int o = 16; o > 0; o >>= 1) vs += __shfl_xor_sync(0xffffffffu, vs, o);
    float inv = rsqrtf(vs * (1.f / 128.f) + 1e-5f);
#pragma unroll
    for (int j = 0; j < 4; j++) {
        int f = lane + 32 * j;
        out[(size_t)gw * H + f] = (v[j] - mu) * inv * gam[f] + bet[f];
    }
}

// ---------------- launch -------------------------------------------------------
extern "C" void kernel_launch(void* const* d_in, const int* in_sizes, int n_in,
                              void* d_out, int out_size) {
    const float* h   = (const float*)d_in[0];
    const float* co  = (const float*)d_in[1];
    const float* ea  = (const float*)d_in[2];
    const int*   ed  = (const int*)d_in[3];
    const float* ew1 = (const float*)d_in[4];
    const float* eb1 = (const float*)d_in[5];
    const float* ew2 = (const float*)d_in[6];
    const float* eb2 = (const float*)d_in[7];
    const float* nw1 = (const float*)d_in[8];
    const float* nb1 = (const float*)d_in[9];
    const float* nw2 = (const float*)d_in[10];
    const float* nb2 = (const float*)d_in[11];
    const float* lng = (const float*)d_in[12];
    const float* lnb = (const float*)d_in[13];
    float* out = (float*)d_out;

    cudaFuncSetAttribute(k_pq,   cudaFuncAttributeMaxDynamicSharedMemorySize, PQ_SMEM);
    cudaFuncSetAttribute(k_edge, cudaFuncAttributeMaxDynamicSharedMemorySize, EDGE_SMEM);
    cudaFuncSetAttribute(k_node, cudaFuncAttributeMaxDynamicSharedMemorySize, NODE_SMEM);

    // one-time per-call prep
    k_copy_h<<<2500, 256>>>(h);
    k_radial<<<1250, 256>>>(co, ed);
    k_cvt<<<289, 512>>>(ew1, NL * 289 * H, 0);
    k_cvt<<<128, 512>>>(ew2, NL * H * H, 1);
    k_cvt<<<256, 512>>>(nw1, NL * 2 * H * H, 2);
    k_cvt<<<128, 512>>>(nw2, NL * H * H, 3);

    for (int i = 0; i < NL; i++) {
        const float* ew1i = ew1 + (size_t)i * 289 * H;
        k_zero_agg<<<2500, 256>>>();
        k_pq<<<dim3(313, 2), 256, PQ_SMEM>>>(i);
        k_edge<<<NE / 128, 512, EDGE_SMEM>>>(ed, ea, ew1i,
                                             eb1 + i * H, eb2 + i * H, i);
        k_node<<<313, 256, NODE_SMEM>>>(nb1 + i * H, nb2 + i * H, i, i > 0);
    }
    k_ln<<<2500, 256>>>(lng, lnb, out);
}

// round 5
// speedup vs baseline: 2.7512x; 2.4859x over previous
#include <cuda_runtime.h>
#include <cstdint>

#define NN 20000
#define NE 320000
#define H 128
#define DE 32
#define NL 4
#define EB 64   // edges per block in k_edge

// ---------------- scratch (device globals) -----------------------------------
__device__ float g_radial[NE];
__device__ float g_P[NN * H];
__device__ float g_Q[NN * H];
__device__ float g_agg[NN * H];
__device__ float g_h[NN * H];
// tf32-rounded weight copies
__device__ float g_ew1t[NL * 289 * H];
__device__ float g_w2t[NL * H * H];
__device__ float g_nw1t[NL * 2 * H * H];
__device__ float g_nw2t[NL * H * H];

// ---------------- helpers -----------------------------------------------------
__device__ __forceinline__ float siluf(float x) {
    return x * (1.0f / (1.0f + __expf(-x)));
}
__device__ __forceinline__ float4 add4(float4 a, float4 b) {
    return make_float4(a.x + b.x, a.y + b.y, a.z + b.z, a.w + b.w);
}
__device__ __forceinline__ float4 silu4(float4 v) {
    v.x = siluf(v.x); v.y = siluf(v.y); v.z = siluf(v.z); v.w = siluf(v.w);
    return v;
}
__device__ __forceinline__ float tf32r(float x) {
    unsigned int u;
    asm("cvt.rna.tf32.f32 %0, %1;" : "=r"(u) : "f"(x));
    return __uint_as_float(u);
}
__device__ __forceinline__ unsigned int fb(float x) { return __float_as_uint(x); }

__device__ __forceinline__ void mma8(float* d, unsigned int a0, unsigned int a1,
                                     unsigned int a2, unsigned int a3,
                                     unsigned int b0, unsigned int b1) {
    asm volatile(
        "mma.sync.aligned.m16n8k8.row.col.f32.tf32.tf32.f32 "
        "{%0,%1,%2,%3},{%4,%5,%6,%7},{%8,%9},{%0,%1,%2,%3};\n"
        : "+f"(d[0]), "+f"(d[1]), "+f"(d[2]), "+f"(d[3])
        : "r"(a0), "r"(a1), "r"(a2), "r"(a3), "r"(b0), "r"(b1));
}

// ---------------- tiny utility kernels ----------------------------------------
__global__ void k_copy_h(const float* __restrict__ h) {
    int i = blockIdx.x * blockDim.x + threadIdx.x;
    ((float4*)g_h)[i] = ((const float4*)h)[i];
}
__global__ void k_zero_agg() {
    int i = blockIdx.x * blockDim.x + threadIdx.x;
    ((float4*)g_agg)[i] = make_float4(0.f, 0.f, 0.f, 0.f);
}
__global__ void k_radial(const float* __restrict__ coords, const int* __restrict__ edges) {
    int e = blockIdx.x * blockDim.x + threadIdx.x;
    if (e >= NE) return;
    int r = edges[e], c = edges[NE + e];
    float dx = coords[3 * r]     - coords[3 * c];
    float dy = coords[3 * r + 1] - coords[3 * c + 1];
    float dz = coords[3 * r + 2] - coords[3 * c + 2];
    g_radial[e] = dx * dx + dy * dy + dz * dz;
}
// single launch: convert all weight tensors to tf32-rounded copies
__global__ void k_cvt_all(const float* __restrict__ ew1, const float* __restrict__ ew2,
                          const float* __restrict__ nw1, const float* __restrict__ nw2) {
    int t0 = blockIdx.x * blockDim.x + threadIdx.x;
    int stride = gridDim.x * blockDim.x;
    for (int i = t0; i < NL * 289 * H; i += stride) g_ew1t[i] = tf32r(ew1[i]);
    for (int i = t0; i < NL * H * H; i += stride)   g_w2t[i]  = tf32r(ew2[i]);
    for (int i = t0; i < NL * 2 * H * H; i += stride) g_nw1t[i] = tf32r(nw1[i]);
    for (int i = t0; i < NL * H * H; i += stride)   g_nw2t[i] = tf32r(nw2[i]);
}

// ---------------- k_pq: P = h @ W1a, Q = h @ W1b (tf32 mma) -------------------
#define PQ_SMEM ((64 * 132 + 128 * 132) * 4)
__global__ __launch_bounds__(256) void k_pq(int lyr) {
    extern __shared__ float sm[];
    float* As = sm;                 // [64][132] tf32(h)
    float* Bs = sm + 64 * 132;      // [128][132] tf32 weights
    int tid = threadIdx.x;
    int m0 = blockIdx.x * 64;
    const float* B = g_ew1t + (size_t)lyr * 289 * H + (size_t)blockIdx.y * H * H;
    float* C = blockIdx.y ? g_Q : g_P;

#pragma unroll
    for (int i = 0; i < 8; i++) {
        int id = tid + 256 * i;
        int r = id >> 5, cv = id & 31;
        int n = m0 + r;
        float4 v = (n < NN) ? ((const float4*)(g_h + (size_t)n * H))[cv]
                            : make_float4(0.f, 0.f, 0.f, 0.f);
        v.x = tf32r(v.x); v.y = tf32r(v.y); v.z = tf32r(v.z); v.w = tf32r(v.w);
        ((float4*)(As + r * 132))[cv] = v;
    }
#pragma unroll
    for (int i = 0; i < 16; i++) {
        int id = tid + 256 * i;
        int r = id >> 5, cv = id & 31;
        ((float4*)(Bs + r * 132))[cv] = ((const float4*)(B + (size_t)r * H))[cv];
    }
    __syncthreads();

    int wid = tid >> 5, lane = tid & 31;
    int warpM = wid & 3, warpN = wid >> 2;
    int g = lane >> 2, t = lane & 3;
    int r0 = warpM * 16, n0 = warpN * 64;
    const float* A0 = As + (r0 + g) * 132;
    const float* A1 = As + (r0 + g + 8) * 132;
    const float* Bp = Bs + t * 132 + n0 + g;

    float acc[8][4];
#pragma unroll
    for (int nf = 0; nf < 8; nf++)
#pragma unroll
        for (int j = 0; j < 4; j++) acc[nf][j] = 0.f;

#pragma unroll
    for (int k0 = 0; k0 < 128; k0 += 8) {
        unsigned int a0 = fb(A0[k0 + t]),     a1 = fb(A1[k0 + t]);
        unsigned int a2 = fb(A0[k0 + t + 4]), a3 = fb(A1[k0 + t + 4]);
#pragma unroll
        for (int nf = 0; nf < 8; nf++) {
            unsigned int b0 = fb(Bp[k0 * 132 + nf * 8]);
            unsigned int b1 = fb(Bp[(k0 + 4) * 132 + nf * 8]);
            mma8(acc[nf], a0, a1, a2, a3, b0, b1);
        }
    }
    int ng  = m0 + r0 + g;
    int ng8 = ng + 8;
#pragma unroll
    for (int nf = 0; nf < 8; nf++) {
        int col = n0 + nf * 8 + 2 * t;
        if (ng < NN)
            *(float2*)(C + (size_t)ng * H + col)  = make_float2(acc[nf][0], acc[nf][1]);
        if (ng8 < NN)
            *(float2*)(C + (size_t)ng8 * H + col) = make_float2(acc[nf][2], acc[nf][3]);
    }
}

// ---------------- k_edge (redesigned) ------------------------------------------
// 64 edges/block, 256 threads, ~100KB smem -> 2 blocks/SM.
// phase1: mma X[64x40] @ W1c[40x128] (tf32) + P/Q fragment gathers + silu -> Sh
// phase2: mma Sh[64x128] @ W2[128x128] (tf32), W2 double-buffered 32-row chunks
// phase3: silu(+b2), shfl-paired float4 atomic scatter into g_agg
#define EDGE_SMEM ((64 * 44 + 40 * 132 + 64 * 132 + 2 * 32 * 132) * 4 + 2 * EB * 4)

__global__ __launch_bounds__(256, 2) void k_edge(
    const int* __restrict__ edges, const float* __restrict__ edge_attr,
    const float* __restrict__ eb1, const float* __restrict__ eb2, int lyr) {
    extern __shared__ float sm[];
    float* xs   = sm;                               // [64][44] tf32 X (padded K=40)
    float* W1cs = sm + 64 * 44;                     // [40][132] tf32
    float* Sh   = W1cs + 40 * 132;                  // [64][132] tf32 hidden
    float* W2d  = Sh + 64 * 132;                    // [2][32][132] tf32 chunks
    int*   rs   = (int*)(W2d + 2 * 32 * 132);       // [64]
    int*   cs   = rs + EB;

    int tid = threadIdx.x;
    int e0 = blockIdx.x * EB;

    // ---- phase 0: stage X, W1c; zero pads
    if (tid < EB) {
        rs[tid] = edges[e0 + tid];
        cs[tid] = edges[NE + e0 + tid];
        xs[tid * 44] = tf32r(g_radial[e0 + tid]);
#pragma unroll
        for (int j = 33; j < 40; j++) xs[tid * 44 + j] = 0.f;
    }
#pragma unroll
    for (int i = 0; i < 2; i++) {                   // edge_attr: 64 x 8 float4
        int id = tid + 256 * i;
        int e = id >> 3, cv = id & 7;
        float4 v = ((const float4*)(edge_attr + (size_t)(e0 + e) * DE))[cv];
        float* xp = xs + e * 44 + 1 + cv * 4;
        xp[0] = tf32r(v.x); xp[1] = tf32r(v.y); xp[2] = tf32r(v.z); xp[3] = tf32r(v.w);
    }
    {
        const float* W1c = g_ew1t + (size_t)lyr * 289 * H + 256 * H;
#pragma unroll
        for (int i = 0; i < 5; i++) {               // rows 0..32: 33 x 32 float4
            int id = tid + 256 * i;
            if (id < 33 * 32) {
                int r = id >> 5, cv = id & 31;
                ((float4*)(W1cs + r * 132))[cv] = ((const float4*)(W1c + (size_t)r * H))[cv];
            }
        }
#pragma unroll
        for (int i = 0; i < 4; i++) {               // rows 33..39: zero 7*128
            int id = tid + 256 * i;
            if (id < 7 * 128) W1cs[(33 + (id >> 7)) * 132 + (id & 127)] = 0.f;
        }
    }
    __syncthreads();

    int wid = tid >> 5, lane = tid & 31;
    int warpM = wid & 3, warpN = wid >> 2;
    int g = lane >> 2, t = lane & 3;
    int r0 = warpM * 16, n0 = warpN * 64;

    // ---- phase 1: X @ W1c via mma, bias in acc, + P/Q gathers, silu -> Sh
    {
        float acc[8][4];
#pragma unroll
        for (int nf = 0; nf < 8; nf++) {
            float2 b = *(const float2*)(eb1 + n0 + nf * 8 + 2 * t);
            acc[nf][0] = b.x; acc[nf][1] = b.y; acc[nf][2] = b.x; acc[nf][3] = b.y;
        }
        const float* A0 = xs + (r0 + g) * 44;
        const float* A1 = A0 + 8 * 44;
        const float* Bp = W1cs + t * 132 + n0 + g;
#pragma unroll
        for (int k0 = 0; k0 < 40; k0 += 8) {
            unsigned int a0 = fb(A0[k0 + t]),     a1 = fb(A1[k0 + t]);
            unsigned int a2 = fb(A0[k0 + t + 4]), a3 = fb(A1[k0 + t + 4]);
#pragma unroll
            for (int nf = 0; nf < 8; nf++) {
                unsigned int b0 = fb(Bp[k0 * 132 + nf * 8]);
                unsigned int b1 = fb(Bp[(k0 + 4) * 132 + nf * 8]);
                mma8(acc[nf], a0, a1, a2, a3, b0, b1);
            }
        }
        int rA = rs[r0 + g], rB = rs[r0 + g + 8];
        int cA = cs[r0 + g], cB = cs[r0 + g + 8];
        const float* PA = g_P + (size_t)rA * H;
        const float* QA = g_Q + (size_t)cA * H;
        const float* PB = g_P + (size_t)rB * H;
        const float* QB = g_Q + (size_t)cB * H;
        float* S0 = Sh + (r0 + g) * 132;
        float* S1 = S0 + 8 * 132;
#pragma unroll
        for (int nf = 0; nf < 8; nf++) {
            int col = n0 + nf * 8 + 2 * t;
            float2 pa = *(const float2*)(PA + col), qa = *(const float2*)(QA + col);
            float2 pb = *(const float2*)(PB + col), qb = *(const float2*)(QB + col);
            float v0 = acc[nf][0] + pa.x + qa.x;
            float v1 = acc[nf][1] + pa.y + qa.y;
            float v2 = acc[nf][2] + pb.x + qb.x;
            float v3 = acc[nf][3] + pb.y + qb.y;
            *(float2*)(S0 + col) = make_float2(tf32r(siluf(v0)), tf32r(siluf(v1)));
            *(float2*)(S1 + col) = make_float2(tf32r(siluf(v2)), tf32r(siluf(v3)));
        }
    }
    __syncthreads();

    // ---- phase 2: Sh @ W2, W2 double-buffered 32-row chunks
    const float* W2 = g_w2t + (size_t)lyr * H * H;
#pragma unroll
    for (int i = 0; i < 4; i++) {                   // preload chunk 0
        int id = tid + 256 * i;
        int r = id >> 5, cv = id & 31;
        ((float4*)(W2d + r * 132))[cv] = ((const float4*)(W2 + (size_t)r * H))[cv];
    }
    __syncthreads();

    float acc2[8][4];
#pragma unroll
    for (int nf = 0; nf < 8; nf++)
#pragma unroll
        for (int j = 0; j < 4; j++) acc2[nf][j] = 0.f;

    const float* A0s = Sh + (r0 + g) * 132;
    const float* A1s = A0s + 8 * 132;

#pragma unroll
    for (int c = 0; c < 4; c++) {
        const float* cur = W2d + (c & 1) * 32 * 132;
        float4 pf[4];
        if (c < 3) {                                // prefetch chunk c+1 into regs
#pragma unroll
            for (int i = 0; i < 4; i++) {
                int id = tid + 256 * i;
                int r = id >> 5, cv = id & 31;
                pf[i] = ((const float4*)(W2 + (size_t)((c + 1) * 32 + r) * H))[cv];
            }
        }
        const float* Bp2 = cur + t * 132 + n0 + g;
#pragma unroll
        for (int k0 = 0; k0 < 32; k0 += 8) {
            int kk = c * 32 + k0;
            unsigned int a0 = fb(A0s[kk + t]),     a1 = fb(A1s[kk + t]);
            unsigned int a2 = fb(A0s[kk + t + 4]), a3 = fb(A1s[kk + t + 4]);
#pragma unroll
            for (int nf = 0; nf < 8; nf++) {
                unsigned int b0 = fb(Bp2[k0 * 132 + nf * 8]);
                unsigned int b1 = fb(Bp2[(k0 + 4) * 132 + nf * 8]);
                mma8(acc2[nf], a0, a1, a2, a3, b0, b1);
            }
        }
        if (c < 3) {
            float* nxt = W2d + ((c + 1) & 1) * 32 * 132;
#pragma unroll
            for (int i = 0; i < 4; i++) {
                int id = tid + 256 * i;
                int r = id >> 5, cv = id & 31;
                ((float4*)(nxt + r * 132))[cv] = pf[i];
            }
            __syncthreads();
        }
    }

    // ---- phase 3: pack via shfl, bias+silu, float4 atomic scatter
    {
        bool odd = (t & 1);
        int node = odd ? rs[r0 + g + 8] : rs[r0 + g];
#pragma unroll
        for (int nf = 0; nf < 8; nf++) {
            float px = odd ? acc2[nf][0] : acc2[nf][2];
            float py = odd ? acc2[nf][1] : acc2[nf][3];
            float rx = __shfl_xor_sync(0xffffffffu, px, 1);
            float ry = __shfl_xor_sync(0xffffffffu, py, 1);
            float4 v;
            int col;
            if (!odd) {
                v = make_float4(acc2[nf][0], acc2[nf][1], rx, ry);
                col = n0 + nf * 8 + 2 * t;
            } else {
                v = make_float4(rx, ry, acc2[nf][2], acc2[nf][3]);
                col = n0 + nf * 8 + 2 * (t - 1);
            }
            float4 b = *(const float4*)(eb2 + col);
            v = silu4(add4(v, b));
            atomicAdd((float4*)(g_agg + (size_t)node * H + col), v);
        }
    }
}

// ---------------- k_node: fused [h|agg]@nw1 -> silu -> @nw2 (+res), tf32 mma --
#define NODE_SMEM ((64 * 260 + 256 * 132) * 4)
__global__ __launch_bounds__(256) void k_node(
    const float* __restrict__ nb1, const float* __restrict__ nb2,
    int lyr, int residual) {
    extern __shared__ float sm[];
    float* As  = sm;                  // [64][260] tf32([h|agg]); later Ss [64][132]
    float* Bs  = sm + 64 * 260;       // [256][132] nw1t; later [128][132] nw2t
    int tid = threadIdx.x;
    int m0 = blockIdx.x * 64;

#pragma unroll
    for (int i = 0; i < 16; i++) {
        int id = tid + 256 * i;
        int r = id >> 6, cv = id & 63;
        int n = m0 + r;
        const float* src = (cv < 32) ? (g_h + (size_t)n * H + cv * 4)
                                     : (g_agg + (size_t)n * H + (cv - 32) * 4);
        float4 v = (n < NN) ? *(const float4*)src : make_float4(0.f, 0.f, 0.f, 0.f);
        v.x = tf32r(v.x); v.y = tf32r(v.y); v.z = tf32r(v.z); v.w = tf32r(v.w);
        float* dst = As + r * 260 + cv * 4;
        dst[0] = v.x; dst[1] = v.y; dst[2] = v.z; dst[3] = v.w;
    }
    {
        const float* B = g_nw1t + (size_t)lyr * 2 * H * H;
#pragma unroll
        for (int i = 0; i < 32; i++) {
            int id = tid + 256 * i;
            int r = id >> 5, cv = id & 31;
            ((float4*)(Bs + r * 132))[cv] = ((const float4*)(B + (size_t)r * H))[cv];
        }
    }
    __syncthreads();

    int wid = tid >> 5, lane = tid & 31;
    int warpM = wid & 3, warpN = wid >> 2;
    int g = lane >> 2, t = lane & 3;
    int r0 = warpM * 16, n0 = warpN * 64;

    float acc[8][4];
#pragma unroll
    for (int nf = 0; nf < 8; nf++)
#pragma unroll
        for (int j = 0; j < 4; j++) acc[nf][j] = 0.f;

    {   // GEMM1: K = 256
        const float* A0 = As + (r0 + g) * 260;
        const float* A1 = As + (r0 + g + 8) * 260;
        const float* Bp = Bs + t * 132 + n0 + g;
#pragma unroll
        for (int k0 = 0; k0 < 256; k0 += 8) {
            unsigned int a0 = fb(A0[k0 + t]),     a1 = fb(A1[k0 + t]);
            unsigned int a2 = fb(A0[k0 + t + 4]), a3 = fb(A1[k0 + t + 4]);
#pragma unroll
            for (int nf = 0; nf < 8; nf++) {
                unsigned int b0 = fb(Bp[k0 * 132 + nf * 8]);
                unsigned int b1 = fb(Bp[(k0 + 4) * 132 + nf * 8]);
                mma8(acc[nf], a0, a1, a2, a3, b0, b1);
            }
        }
    }
    __syncthreads();

    {   // epilogue 1: silu(+b1) -> Ss (tf32), load Bs2
        float* Ss = As;
#pragma unroll
        for (int nf = 0; nf < 8; nf++) {
            int col = n0 + nf * 8 + 2 * t;
            float2 b = *(const float2*)(nb1 + col);
            float* s0 = Ss + (r0 + g) * 132 + col;
            float* s1 = Ss + (r0 + g + 8) * 132 + col;
            s0[0] = tf32r(siluf(acc[nf][0] + b.x));
            s0[1] = tf32r(siluf(acc[nf][1] + b.y));
            s1[0] = tf32r(siluf(acc[nf][2] + b.x));
            s1[1] = tf32r(siluf(acc[nf][3] + b.y));
        }
        const float* B = g_nw2t + (size_t)lyr * H * H;
#pragma unroll
        for (int i = 0; i < 16; i++) {
            int id = tid + 256 * i;
            int r = id >> 5, cv = id & 31;
            ((float4*)(Bs + r * 132))[cv] = ((const float4*)(B + (size_t)r * H))[cv];
        }
    }
    __syncthreads();

    {   // GEMM2: K = 128
#pragma unroll
        for (int nf = 0; nf < 8; nf++)
#pragma unroll
            for (int j = 0; j < 4; j++) acc[nf][j] = 0.f;
        const float* Ss = As;
        const float* A0 = Ss + (r0 + g) * 132;
        const float* A1 = Ss + (r0 + g + 8) * 132;
        const float* Bp = Bs + t * 132 + n0 + g;
#pragma unroll
        for (int k0 = 0; k0 < 128; k0 += 8) {
            unsigned int a0 = fb(A0[k0 + t]),     a1 = fb(A1[k0 + t]);
            unsigned int a2 = fb(A0[k0 + t + 4]), a3 = fb(A1[k0 + t + 4]);
#pragma unroll
            for (int nf = 0; nf < 8; nf++) {
                unsigned int b0 = fb(Bp[k0 * 132 + nf * 8]);
                unsigned int b1 = fb(Bp[(k0 + 4) * 132 + nf * 8]);
                mma8(acc[nf], a0, a1, a2, a3, b0, b1);
            }
        }
    }

    int ng  = m0 + r0 + g;
    int ng8 = ng + 8;
#pragma unroll
    for (int nf = 0; nf < 8; nf++) {
        int col = n0 + nf * 8 + 2 * t;
        float2 b = *(const float2*)(nb2 + col);
        if (ng < NN) {
            float2* hp = (float2*)(g_h + (size_t)ng * H + col);
            float2 o = make_float2(acc[nf][0] + b.x, acc[nf][1] + b.y);
            if (residual) { float2 old = *hp; o.x += old.x; o.y += old.y; }
            *hp = o;
        }
        if (ng8 < NN) {
            float2* hp = (float2*)(g_h + (size_t)ng8 * H + col);
            float2 o = make_float2(acc[nf][2] + b.x, acc[nf][3] + b.y);
            if (residual) { float2 old = *hp; o.x += old.x; o.y += old.y; }
            *hp = o;
        }
    }
}

// ---------------- final LayerNorm ---------------------------------------------
__global__ void k_ln(const float* __restrict__ gam, const float* __restrict__ bet,
                     float* __restrict__ out) {
    int gw = (blockIdx.x * blockDim.x + threadIdx.x) >> 5;
    int lane = threadIdx.x & 31;
    if (gw >= NN) return;
    const float* hr = g_h + (size_t)gw * H;
    float v[4];
    float s = 0.f;
#pragma unroll
    for (int j = 0; j < 4; j++) { v[j] = hr[lane + 32 * j]; s += v[j]; }
#pragma unroll
    for (int o = 16; o > 0; o >>= 1) s += __shfl_xor_sync(0xffffffffu, s, o);
    float mu = s * (1.f / 128.f);
    float vs = 0.f;
#pragma unroll
    for (int j = 0; j < 4; j++) { float d = v[j] - mu; vs += d * d; }
#pragma unroll
    for (int o = 16; o > 0; o >>= 1) vs += __shfl_xor_sync(0xffffffffu, vs, o);
    float inv = rsqrtf(vs * (1.f / 128.f) + 1e-5f);
#pragma unroll
    for (int j = 0; j < 4; j++) {
        int f = lane + 32 * j;
        out[(size_t)gw * H + f] = (v[j] - mu) * inv * gam[f] + bet[f];
    }
}

// ---------------- launch -------------------------------------------------------
extern "C" void kernel_launch(void* const* d_in, const int* in_sizes, int n_in,
                              void* d_out, int out_size) {
    const float* h   = (const float*)d_in[0];
    const float* co  = (const float*)d_in[1];
    const float* ea  = (const float*)d_in[2];
    const int*   ed  = (const int*)d_in[3];
    const float* ew1 = (const float*)d_in[4];
    const float* eb1 = (const float*)d_in[5];
    const float* ew2 = (const float*)d_in[6];
    const float* eb2 = (const float*)d_in[7];
    const float* nw1 = (const float*)d_in[8];
    const float* nb1 = (const float*)d_in[9];
    const float* nw2 = (const float*)d_in[10];
    const float* nb2 = (const float*)d_in[11];
    const float* lng = (const float*)d_in[12];
    const float* lnb = (const float*)d_in[13];
    float* out = (float*)d_out;

    cudaFuncSetAttribute(k_pq,   cudaFuncAttributeMaxDynamicSharedMemorySize, PQ_SMEM);
    cudaFuncSetAttribute(k_edge, cudaFuncAttributeMaxDynamicSharedMemorySize, EDGE_SMEM);
    cudaFuncSetAttribute(k_node, cudaFuncAttributeMaxDynamicSharedMemorySize, NODE_SMEM);

    // prep (3 launches, so launch #6 = first k_edge for ncu -s 5 -c 1)
    k_copy_h<<<2500, 256>>>(h);
    k_radial<<<1250, 256>>>(co, ed);
    k_cvt_all<<<256, 512>>>(ew1, ew2, nw1, nw2);

    for (int i = 0; i < NL; i++) {
        k_zero_agg<<<2500, 256>>>();
        k_pq<<<dim3(313, 2), 256, PQ_SMEM>>>(i);
        k_edge<<<NE / EB, 256, EDGE_SMEM>>>(ed, ea, eb1 + i * H, eb2 + i * H, i);
        k_node<<<313, 256, NODE_SMEM>>>(nb1 + i * H, nb2 + i * H, i, i > 0);
    }
    k_ln<<<2500, 256>>>(lng, lnb, out);
}

// round 7
// speedup vs baseline: 2.9539x; 1.0737x over previous
#include <cuda_runtime.h>
#include <cstdint>

#define NN 20000
#define NE 320000
#define H 128
#define DE 32
#define NL 4
#define ETILE 128               // edges per tile in k_edge
#define NTILES (NE / ETILE)     // 2500

// ---------------- scratch (device globals) -----------------------------------
__device__ float g_radial[NE];
__device__ float g_P[NN * H];
__device__ float g_Q[NN * H];
__device__ float g_agg[NN * H];
__device__ float g_h[NN * H];
__device__ float g_ew1t[NL * 289 * H];
__device__ float g_w2t[NL * H * H];
__device__ float g_nw1t[NL * 2 * H * H];
__device__ float g_nw2t[NL * H * H];

// ---------------- helpers -----------------------------------------------------
__device__ __forceinline__ float siluf(float x) {
    return x * (1.0f / (1.0f + __expf(-x)));
}
__device__ __forceinline__ float4 add4(float4 a, float4 b) {
    return make_float4(a.x + b.x, a.y + b.y, a.z + b.z, a.w + b.w);
}
__device__ __forceinline__ float4 silu4(float4 v) {
    v.x = siluf(v.x); v.y = siluf(v.y); v.z = siluf(v.z); v.w = siluf(v.w);
    return v;
}
__device__ __forceinline__ float tf32r(float x) {
    unsigned int u;
    asm("cvt.rna.tf32.f32 %0, %1;" : "=r"(u) : "f"(x));
    return __uint_as_float(u);
}
__device__ __forceinline__ unsigned int fb(float x) { return __float_as_uint(x); }

__device__ __forceinline__ void mma8(float* d, unsigned int a0, unsigned int a1,
                                     unsigned int a2, unsigned int a3,
                                     unsigned int b0, unsigned int b1) {
    asm volatile(
        "mma.sync.aligned.m16n8k8.row.col.f32.tf32.tf32.f32 "
        "{%0,%1,%2,%3},{%4,%5,%6,%7},{%8,%9},{%0,%1,%2,%3};\n"
        : "+f"(d[0]), "+f"(d[1]), "+f"(d[2]), "+f"(d[3])
        : "r"(a0), "r"(a1), "r"(a2), "r"(a3), "r"(b0), "r"(b1));
}

// ---------------- prep: copy h, zero agg, radial (one launch) ------------------
__global__ void k_prep(const float* __restrict__ h, const float* __restrict__ coords,
                       const int* __restrict__ edges) {
    int i = blockIdx.x * blockDim.x + threadIdx.x;   // 640000 threads
    ((float4*)g_h)[i] = ((const float4*)h)[i];
    ((float4*)g_agg)[i] = make_float4(0.f, 0.f, 0.f, 0.f);
    if (i < NE) {
        int r = edges[i], c = edges[NE + i];
        float dx = coords[3 * r]     - coords[3 * c];
        float dy = coords[3 * r + 1] - coords[3 * c + 1];
        float dz = coords[3 * r + 2] - coords[3 * c + 2];
        g_radial[i] = dx * dx + dy * dy + dz * dz;
    }
}

// single launch: convert all weight tensors to tf32-rounded copies
__global__ void k_cvt_all(const float* __restrict__ ew1, const float* __restrict__ ew2,
                          const float* __restrict__ nw1, const float* __restrict__ nw2) {
    int t0 = blockIdx.x * blockDim.x + threadIdx.x;
    int stride = gridDim.x * blockDim.x;
    for (int i = t0; i < NL * 289 * H; i += stride) g_ew1t[i] = tf32r(ew1[i]);
    for (int i = t0; i < NL * H * H; i += stride)   g_w2t[i]  = tf32r(ew2[i]);
    for (int i = t0; i < NL * 2 * H * H; i += stride) g_nw1t[i] = tf32r(nw1[i]);
    for (int i = t0; i < NL * H * H; i += stride)   g_nw2t[i] = tf32r(nw2[i]);
}

// ---------------- k_pq: P = h @ W1a, Q = h @ W1b (tf32 mma) -------------------
#define PQ_SMEM ((64 * 132 + 128 * 132) * 4)
__global__ __launch_bounds__(256) void k_pq(int lyr) {
    extern __shared__ float sm[];
    float* As = sm;                 // [64][132]
    float* Bs = sm + 64 * 132;      // [128][132]
    int tid = threadIdx.x;
    int m0 = blockIdx.x * 64;
    const float* B = g_ew1t + (size_t)lyr * 289 * H + (size_t)blockIdx.y * H * H;
    float* C = blockIdx.y ? g_Q : g_P;

#pragma unroll
    for (int i = 0; i < 8; i++) {
        int id = tid + 256 * i;
        int r = id >> 5, cv = id & 31;
        int n = m0 + r;
        float4 v = (n < NN) ? ((const float4*)(g_h + (size_t)n * H))[cv]
                            : make_float4(0.f, 0.f, 0.f, 0.f);
        v.x = tf32r(v.x); v.y = tf32r(v.y); v.z = tf32r(v.z); v.w = tf32r(v.w);
        ((float4*)(As + r * 132))[cv] = v;
    }
#pragma unroll
    for (int i = 0; i < 16; i++) {
        int id = tid + 256 * i;
        int r = id >> 5, cv = id & 31;
        ((float4*)(Bs + r * 132))[cv] = ((const float4*)(B + (size_t)r * H))[cv];
    }
    __syncthreads();

    int wid = tid >> 5, lane = tid & 31;
    int warpM = wid & 3, warpN = wid >> 2;
    int g = lane >> 2, t = lane & 3;
    int r0 = warpM * 16, n0 = warpN * 64;
    const float* A0 = As + (r0 + g) * 132;
    const float* A1 = As + (r0 + g + 8) * 132;
    const float* Bp = Bs + t * 132 + n0 + g;

    float acc[8][4];
#pragma unroll
    for (int nf = 0; nf < 8; nf++)
#pragma unroll
        for (int j = 0; j < 4; j++) acc[nf][j] = 0.f;

#pragma unroll
    for (int k0 = 0; k0 < 128; k0 += 8) {
        unsigned int a0 = fb(A0[k0 + t]),     a1 = fb(A1[k0 + t]);
        unsigned int a2 = fb(A0[k0 + t + 4]), a3 = fb(A1[k0 + t + 4]);
#pragma unroll
        for (int nf = 0; nf < 8; nf++) {
            unsigned int b0 = fb(Bp[k0 * 132 + nf * 8]);
            unsigned int b1 = fb(Bp[(k0 + 4) * 132 + nf * 8]);
            mma8(acc[nf], a0, a1, a2, a3, b0, b1);
        }
    }
    int ng  = m0 + r0 + g;
    int ng8 = ng + 8;
#pragma unroll
    for (int nf = 0; nf < 8; nf++) {
        int col = n0 + nf * 8 + 2 * t;
        if (ng < NN)
            *(float2*)(C + (size_t)ng * H + col)  = make_float2(acc[nf][0], acc[nf][1]);
        if (ng8 < NN)
            *(float2*)(C + (size_t)ng8 * H + col) = make_float2(acc[nf][2], acc[nf][3]);
    }
}

// ---------------- k_edge: persistent, W1c+W2 staged once -----------------------
// 148 blocks x 512 threads; each block loops over tiles of 128 edges.
// smem: xs[128][44] + W1c[40][132] + Sh[128][132] + W2[128][132] + rs/cs
#define EDGE_SMEM ((128 * 44 + 40 * 132 + 128 * 132 + 128 * 132) * 4 + 2 * ETILE * 4)

__global__ __launch_bounds__(512, 1) void k_edge(
    const int* __restrict__ edges, const float* __restrict__ edge_attr,
    const float* __restrict__ eb1, const float* __restrict__ eb2, int lyr) {
    extern __shared__ float sm[];
    float* xs   = sm;                               // [128][44]
    float* W1cs = sm + 128 * 44;                    // [40][132]
    float* Sh   = W1cs + 40 * 132;                  // [128][132]
    float* W2s  = Sh + 128 * 132;                   // [128][132]
    int*   rs   = (int*)(W2s + 128 * 132);          // [128]
    int*   cs   = rs + ETILE;

    int tid = threadIdx.x;

    // ---- stage W1c (rows 0..32 real, 33..39 zero) and W2, once per block
    {
        const float* W1c = g_ew1t + (size_t)lyr * 289 * H + 256 * H;
#pragma unroll
        for (int i = 0; i < 3; i++) {
            int id = tid + 512 * i;
            if (id < 33 * 32) {
                int r = id >> 5, cv = id & 31;
                ((float4*)(W1cs + r * 132))[cv] = ((const float4*)(W1c + (size_t)r * H))[cv];
            }
        }
#pragma unroll
        for (int i = 0; i < 2; i++) {
            int id = tid + 512 * i;
            if (id < 7 * 128) W1cs[(33 + (id >> 7)) * 132 + (id & 127)] = 0.f;
        }
        const float* W2 = g_w2t + (size_t)lyr * H * H;
#pragma unroll
        for (int i = 0; i < 8; i++) {
            int id = tid + 512 * i;
            int r = id >> 5, cv = id & 31;
            ((float4*)(W2s + r * 132))[cv] = ((const float4*)(W2 + (size_t)r * H))[cv];
        }
    }

    int wid = tid >> 5, lane = tid & 31;
    int warpM = wid & 7, warpN = wid >> 3;          // 8 M-groups x 2 N-groups
    int g = lane >> 2, t = lane & 3;
    int r0 = warpM * 16, n0 = warpN * 64;

    for (int tile = blockIdx.x; tile < NTILES; tile += gridDim.x) {
        int e0 = tile * ETILE;
        __syncthreads();   // prior tile's phase2 reads / phase3 rs reads done

        // ---- stage X for this tile
        if (tid < ETILE) {
            rs[tid] = edges[e0 + tid];
            cs[tid] = edges[NE + e0 + tid];
            xs[tid * 44] = tf32r(g_radial[e0 + tid]);
#pragma unroll
            for (int j = 33; j < 40; j++) xs[tid * 44 + j] = 0.f;
        }
#pragma unroll
        for (int i = 0; i < 2; i++) {               // edge_attr: 128 x 8 float4
            int id = tid + 512 * i;
            int e = id >> 3, cv = id & 7;
            float4 v = ((const float4*)(edge_attr + (size_t)(e0 + e) * DE))[cv];
            float* xp = xs + e * 44 + 1 + cv * 4;
            xp[0] = tf32r(v.x); xp[1] = tf32r(v.y); xp[2] = tf32r(v.z); xp[3] = tf32r(v.w);
        }
        __syncthreads();

        // ---- phase 1: X @ W1c (K=40) + bias + P/Q gathers + silu -> Sh
        {
            float acc[8][4];
#pragma unroll
            for (int nf = 0; nf < 8; nf++) {
                float2 b = *(const float2*)(eb1 + n0 + nf * 8 + 2 * t);
                acc[nf][0] = b.x; acc[nf][1] = b.y; acc[nf][2] = b.x; acc[nf][3] = b.y;
            }
            const float* A0 = xs + (r0 + g) * 44;
            const float* A1 = A0 + 8 * 44;
            const float* Bp = W1cs + t * 132 + n0 + g;
#pragma unroll
            for (int k0 = 0; k0 < 40; k0 += 8) {
                unsigned int a0 = fb(A0[k0 + t]),     a1 = fb(A1[k0 + t]);
                unsigned int a2 = fb(A0[k0 + t + 4]), a3 = fb(A1[k0 + t + 4]);
#pragma unroll
                for (int nf = 0; nf < 8; nf++) {
                    unsigned int b0 = fb(Bp[k0 * 132 + nf * 8]);
                    unsigned int b1 = fb(Bp[(k0 + 4) * 132 + nf * 8]);
                    mma8(acc[nf], a0, a1, a2, a3, b0, b1);
                }
            }
            int rA = rs[r0 + g], rB = rs[r0 + g + 8];
            int cA = cs[r0 + g], cB = cs[r0 + g + 8];
            const float* PA = g_P + (size_t)rA * H;
            const float* QA = g_Q + (size_t)cA * H;
            const float* PB = g_P + (size_t)rB * H;
            const float* QB = g_Q + (size_t)cB * H;
            float* S0 = Sh + (r0 + g) * 132;
            float* S1 = S0 + 8 * 132;
#pragma unroll
            for (int nf = 0; nf < 8; nf++) {
                int col = n0 + nf * 8 + 2 * t;
                float2 pa = *(const float2*)(PA + col), qa = *(const float2*)(QA + col);
                float2 pb = *(const float2*)(PB + col), qb = *(const float2*)(QB + col);
                float v0 = acc[nf][0] + pa.x + qa.x;
                float v1 = acc[nf][1] + pa.y + qa.y;
                float v2 = acc[nf][2] + pb.x + qb.x;
                float v3 = acc[nf][3] + pb.y + qb.y;
                *(float2*)(S0 + col) = make_float2(tf32r(siluf(v0)), tf32r(siluf(v1)));
                *(float2*)(S1 + col) = make_float2(tf32r(siluf(v2)), tf32r(siluf(v3)));
            }
        }
        __syncthreads();

        // ---- phase 2: Sh @ W2 (K=128)
        float acc2[8][4];
#pragma unroll
        for (int nf = 0; nf < 8; nf++)
#pragma unroll
            for (int j = 0; j < 4; j++) acc2[nf][j] = 0.f;
        {
            const float* A0s = Sh + (r0 + g) * 132;
            const float* A1s = A0s + 8 * 132;
            const float* Bp2 = W2s + t * 132 + n0 + g;
#pragma unroll
            for (int k0 = 0; k0 < 128; k0 += 8) {
                unsigned int a0 = fb(A0s[k0 + t]),     a1 = fb(A1s[k0 + t]);
                unsigned int a2 = fb(A0s[k0 + t + 4]), a3 = fb(A1s[k0 + t + 4]);
#pragma unroll
                for (int nf = 0; nf < 8; nf++) {
                    unsigned int b0 = fb(Bp2[k0 * 132 + nf * 8]);
                    unsigned int b1 = fb(Bp2[(k0 + 4) * 132 + nf * 8]);
                    mma8(acc2[nf], a0, a1, a2, a3, b0, b1);
                }
            }
        }

        // ---- phase 3: pack via shfl, bias+silu, float4 atomic scatter
        {
            bool odd = (t & 1);
            int node = odd ? rs[r0 + g + 8] : rs[r0 + g];
#pragma unroll
            for (int nf = 0; nf < 8; nf++) {
                float px = odd ? acc2[nf][0] : acc2[nf][2];
                float py = odd ? acc2[nf][1] : acc2[nf][3];
                float rx = __shfl_xor_sync(0xffffffffu, px, 1);
                float ry = __shfl_xor_sync(0xffffffffu, py, 1);
                float4 v;
                int col;
                if (!odd) {
                    v = make_float4(acc2[nf][0], acc2[nf][1], rx, ry);
                    col = n0 + nf * 8 + 2 * t;
                } else {
                    v = make_float4(rx, ry, acc2[nf][2], acc2[nf][3]);
                    col = n0 + nf * 8 + 2 * (t - 1);
                }
                float4 b = *(const float4*)(eb2 + col);
                v = silu4(add4(v, b));
                atomicAdd((float4*)(g_agg + (size_t)node * H + col), v);
            }
        }
    }
}

// ---------------- k_node: fused [h|agg]@nw1 -> silu -> @nw2 (+res) + agg-zero --
#define NODE_SMEM ((64 * 260 + 256 * 132) * 4)
__global__ __launch_bounds__(256) void k_node(
    const float* __restrict__ nb1, const float* __restrict__ nb2,
    int lyr, int residual) {
    extern __shared__ float sm[];
    float* As  = sm;                  // [64][260]; later Ss [64][132]
    float* Bs  = sm + 64 * 260;       // [256][132] nw1t; later [128][132] nw2t
    int tid = threadIdx.x;
    int m0 = blockIdx.x * 64;

#pragma unroll
    for (int i = 0; i < 16; i++) {
        int id = tid + 256 * i;
        int r = id >> 6, cv = id & 63;
        int n = m0 + r;
        const float* src = (cv < 32) ? (g_h + (size_t)n * H + cv * 4)
                                     : (g_agg + (size_t)n * H + (cv - 32) * 4);
        float4 v = (n < NN) ? *(const float4*)src : make_float4(0.f, 0.f, 0.f, 0.f);
        // zero agg for the next layer right after consuming it
        if (cv >= 32 && n < NN)
            *(float4*)(g_agg + (size_t)n * H + (cv - 32) * 4) = make_float4(0.f, 0.f, 0.f, 0.f);
        v.x = tf32r(v.x); v.y = tf32r(v.y); v.z = tf32r(v.z); v.w = tf32r(v.w);
        float* dst = As + r * 260 + cv * 4;
        dst[0] = v.x; dst[1] = v.y; dst[2] = v.z; dst[3] = v.w;
    }
    {
        const float* B = g_nw1t + (size_t)lyr * 2 * H * H;
#pragma unroll
        for (int i = 0; i < 32; i++) {
            int id = tid + 256 * i;
            int r = id >> 5, cv = id & 31;
            ((float4*)(Bs + r * 132))[cv] = ((const float4*)(B + (size_t)r * H))[cv];
        }
    }
    __syncthreads();

    int wid = tid >> 5, lane = tid & 31;
    int warpM = wid & 3, warpN = wid >> 2;
    int g = lane >> 2, t = lane & 3;
    int r0 = warpM * 16, n0 = warpN * 64;

    float acc[8][4];
#pragma unroll
    for (int nf = 0; nf < 8; nf++)
#pragma unroll
        for (int j = 0; j < 4; j++) acc[nf][j] = 0.f;

    {   // GEMM1: K = 256
        const float* A0 = As + (r0 + g) * 260;
        const float* A1 = As + (r0 + g + 8) * 260;
        const float* Bp = Bs + t * 132 + n0 + g;
#pragma unroll
        for (int k0 = 0; k0 < 256; k0 += 8) {
            unsigned int a0 = fb(A0[k0 + t]),     a1 = fb(A1[k0 + t]);
            unsigned int a2 = fb(A0[k0 + t + 4]), a3 = fb(A1[k0 + t + 4]);
#pragma unroll
            for (int nf = 0; nf < 8; nf++) {
                unsigned int b0 = fb(Bp[k0 * 132 + nf * 8]);
                unsigned int b1 = fb(Bp[(k0 + 4) * 132 + nf * 8]);
                mma8(acc[nf], a0, a1, a2, a3, b0, b1);
            }
        }
    }
    __syncthreads();

    {   // epilogue 1: silu(+b1) -> Ss (tf32), load Bs2
        float* Ss = As;
#pragma unroll
        for (int nf = 0; nf < 8; nf++) {
            int col = n0 + nf * 8 + 2 * t;
            float2 b = *(const float2*)(nb1 + col);
            float* s0 = Ss + (r0 + g) * 132 + col;
            float* s1 = Ss + (r0 + g + 8) * 132 + col;
            s0[0] = tf32r(siluf(acc[nf][0] + b.x));
            s0[1] = tf32r(siluf(acc[nf][1] + b.y));
            s1[0] = tf32r(siluf(acc[nf][2] + b.x));
            s1[1] = tf32r(siluf(acc[nf][3] + b.y));
        }
        const float* B = g_nw2t + (size_t)lyr * H * H;
#pragma unroll
        for (int i = 0; i < 16; i++) {
            int id = tid + 256 * i;
            int r = id >> 5, cv = id & 31;
            ((float4*)(Bs + r * 132))[cv] = ((const float4*)(B + (size_t)r * H))[cv];
        }
    }
    __syncthreads();

    {   // GEMM2: K = 128
#pragma unroll
        for (int nf = 0; nf < 8; nf++)
#pragma unroll
            for (int j = 0; j < 4; j++) acc[nf][j] = 0.f;
        const float* Ss = As;
        const float* A0 = Ss + (r0 + g) * 132;
        const float* A1 = Ss + (r0 + g + 8) * 132;
        const float* Bp = Bs + t * 132 + n0 + g;
#pragma unroll
        for (int k0 = 0; k0 < 128; k0 += 8) {
            unsigned int a0 = fb(A0[k0 + t]),     a1 = fb(A1[k0 + t]);
            unsigned int a2 = fb(A0[k0 + t + 4]), a3 = fb(A1[k0 + t + 4]);
#pragma unroll
            for (int nf = 0; nf < 8; nf++) {
                unsigned int b0 = fb(Bp[k0 * 132 + nf * 8]);
                unsigned int b1 = fb(Bp[(k0 + 4) * 132 + nf * 8]);
                mma8(acc[nf], a0, a1, a2, a3, b0, b1);
            }
        }
    }

    int ng  = m0 + r0 + g;
    int ng8 = ng + 8;
#pragma unroll
    for (int nf = 0; nf < 8; nf++) {
        int col = n0 + nf * 8 + 2 * t;
        float2 b = *(const float2*)(nb2 + col);
        if (ng < NN) {
            float2* hp = (float2*)(g_h + (size_t)ng * H + col);
            float2 o = make_float2(acc[nf][0] + b.x, acc[nf][1] + b.y);
            if (residual) { float2 old = *hp; o.x += old.x; o.y += old.y; }
            *hp = o;
        }
        if (ng8 < NN) {
            float2* hp = (float2*)(g_h + (size_t)ng8 * H + col);
            float2 o = make_float2(acc[nf][2] + b.x, acc[nf][3] + b.y);
            if (residual) { float2 old = *hp; o.x += old.x; o.y += old.y; }
            *hp = o;
        }
    }
}

// ---------------- final LayerNorm ---------------------------------------------
__global__ void k_ln(const float* __restrict__ gam, const float* __restrict__ bet,
                     float* __restrict__ out) {
    int gw = (blockIdx.x * blockDim.x + threadIdx.x) >> 5;
    int lane = threadIdx.x & 31;
    if (gw >= NN) return;
    const float* hr = g_h + (size_t)gw * H;
    float v[4];
    float s = 0.f;
#pragma unroll
    for (int j = 0; j < 4; j++) { v[j] = hr[lane + 32 * j]; s += v[j]; }
#pragma unroll
    for (int o = 16; o > 0; o >>= 1) s += __shfl_xor_sync(0xffffffffu, s, o);
    float mu = s * (1.f / 128.f);
    float vs = 0.f;
#pragma unroll
    for (int j = 0; j < 4; j++) { float d = v[j] - mu; vs += d * d; }
#pragma unroll
    for (int o = 16; o > 0; o >>= 1) vs += __shfl_xor_sync(0xffffffffu, vs, o);
    float inv = rsqrtf(vs * (1.f / 128.f) + 1e-5f);
#pragma unroll
    for (int j = 0; j < 4; j++) {
        int f = lane + 32 * j;
        out[(size_t)gw * H + f] = (v[j] - mu) * inv * gam[f] + bet[f];
    }
}

// ---------------- launch -------------------------------------------------------
extern "C" void kernel_launch(void* const* d_in, const int* in_sizes, int n_in,
                              void* d_out, int out_size) {
    const float* h   = (const float*)d_in[0];
    const float* co  = (const float*)d_in[1];
    const float* ea  = (const float*)d_in[2];
    const int*   ed  = (const int*)d_in[3];
    const float* ew1 = (const float*)d_in[4];
    const float* eb1 = (const float*)d_in[5];
    const float* ew2 = (const float*)d_in[6];
    const float* eb2 = (const float*)d_in[7];
    const float* nw1 = (const float*)d_in[8];
    const float* nb1 = (const float*)d_in[9];
    const float* nw2 = (const float*)d_in[10];
    const float* nb2 = (const float*)d_in[11];
    const float* lng = (const float*)d_in[12];
    const float* lnb = (const float*)d_in[13];
    float* out = (float*)d_out;

    cudaFuncSetAttribute(k_pq,   cudaFuncAttributeMaxDynamicSharedMemorySize, PQ_SMEM);
    cudaFuncSetAttribute(k_edge, cudaFuncAttributeMaxDynamicSharedMemorySize, EDGE_SMEM);
    cudaFuncSetAttribute(k_node, cudaFuncAttributeMaxDynamicSharedMemorySize, NODE_SMEM);

    k_prep<<<2500, 256>>>(h, co, ed);
    k_cvt_all<<<256, 512>>>(ew1, ew2, nw1, nw2);

    for (int i = 0; i < NL; i++) {
        k_pq<<<dim3(313, 2), 256, PQ_SMEM>>>(i);
        k_edge<<<148, 512, EDGE_SMEM>>>(ed, ea, eb1 + i * H, eb2 + i * H, i);
        k_node<<<313, 256, NODE_SMEM>>>(nb1 + i * H, nb2 + i * H, i, i > 0);
    }
    k_ln<<<2500, 256>>>(lng, lnb, out);
}